// round 12
// baseline (speedup 1.0000x reference)
#include <cuda_runtime.h>

#define NPTS    4096
#define BATCH   4
#define TPB     256
#define ITILE   2
#define TILE    512                     // square tile side
#define T       (NPTS / TILE)           // 8
#define NSYM    (T * (T + 1) / 2)       // 36
#define NCROSS  (T * T)                 // 64
#define TPB_PAIRS 136                   // tile-pairs per batch
#define TILES   (TPB_PAIRS * BATCH)     // 544 tiles total
#define JP_PER_TILE (TILE / 2)          // 256 j-pair columns per tile
#define JP_TOTAL (TILES * JP_PER_TILE)  // 139264
#define NBLK    592                     // 148 SMs x 4 blocks, uniformly resident
#define WIN     128                     // j-pairs per smem window (= 256 j)

// sqrt(log2(e)): p = x*SCALE  =>  p_i.p_j = log2(e) * x_i.x_j
#define COORD_SCALE 1.2011224087864498f

__device__ float g_partials[NBLK];
__device__ unsigned int g_count = 0;

typedef unsigned long long ull;

__device__ __forceinline__ ull pack2(float lo, float hi) {
    ull r;
    asm("mov.b64 %0, {%1, %2};" : "=l"(r) : "f"(lo), "f"(hi));
    return r;
}
__device__ __forceinline__ void unpack2(ull v, float& lo, float& hi) {
    asm("mov.b64 {%0, %1}, %2;" : "=f"(lo), "=f"(hi) : "l"(v));
}
__device__ __forceinline__ ull fma2(ull a, ull b, ull c) {
    ull d;
    asm("fma.rn.f32x2 %0, %1, %2, %3;" : "=l"(d) : "l"(a), "l"(b), "l"(c));
    return d;
}
__device__ __forceinline__ ull mul2(ull a, ull b) {
    ull d;
    asm("mul.rn.f32x2 %0, %1, %2;" : "=l"(d) : "l"(a), "l"(b));
    return d;
}
__device__ __forceinline__ float ex2(float x) {
    float r;
    asm("ex2.approx.ftz.f32 %0, %1;" : "=f"(r) : "f"(x));
    return r;
}

// j-window layout: per j-pair, 3 float4s (48B):
//   [0]={qx_e,qx_o,qy_e,qy_o} [1]={qz_e,qz_o,mx_e,mx_o} [2]={my_e,my_o,mz_e,mz_o}
// m = n_j * 2^{c_j} (exponent constants folded into normals)

__global__ void __launch_bounds__(TPB, 4)
varifold_fused(const float* __restrict__ xyz1,
               const float* __restrict__ xyz2,
               const float* __restrict__ nor1,
               const float* __restrict__ nor2,
               float* __restrict__ out)
{
    // +3 pad float4s so pipeline prefetch past the last pair is safe
    __shared__ __align__(16) float4 sb[WIN * 3 + 3];
    __shared__ float warpsum[TPB / 32];

    const int tid = threadIdx.x;
    const int bid = blockIdx.x;

    // balanced flat partition of j-pair columns
    const ull p0 = ((ull)bid * JP_TOTAL) / NBLK;
    const ull p1 = ((ull)(bid + 1) * JP_TOTAL) / NBLK;

    float vsum = 0.0f;   // per-thread weighted sum over segments

    ull p = p0;
    while (p < p1) {
        const int tile = (int)(p >> 8);            // 256 j-pairs per tile
        const int pj0  = (int)(p & 255);
        const int rem  = (int)(p1 - p);
        const int pj1  = (pj0 + rem < JP_PER_TILE) ? pj0 + rem : JP_PER_TILE;

        // ---- decode tile -> (batch, term, ti, tj, weight) ----
        const int bt  = tile / TPB_PAIRS;
        int idx = tile - bt * TPB_PAIRS;
        int term, ti, tj;
        float w;
        if (idx < 2 * NSYM) {
            term = (idx < NSYM) ? 0 : 1;
            int k = (idx < NSYM) ? idx : idx - NSYM;
            ti = 0;
            while (k >= T - ti) { k -= T - ti; ti++; }
            tj = ti + k;
            w = (ti == tj) ? 1.0f : 2.0f;          // symmetric: off-diag x2
        } else {
            term = 2;
            const int q = idx - 2 * NSYM;
            ti = q >> 3;                           // T == 8
            tj = q & (T - 1);
            w = -2.0f;
        }

        const float* xa; const float* xb; const float* na; const float* nb;
        if (term == 0)      { xa = xyz1; xb = xyz1; na = nor1; nb = nor1; }
        else if (term == 1) { xa = xyz2; xb = xyz2; na = nor2; nb = nor2; }
        else                { xa = xyz1; xb = xyz2; na = nor1; nb = nor2; }
        const long boff = (long)bt * NPTS * 3;
        xa += boff; xb += boff; na += boff; nb += boff;

        // ---- register-resident i points: p_i, n'_i = n_i * 2^{c_i} ----
        ull px[ITILE], py[ITILE], pz[ITILE];
        ull nx[ITILE], ny[ITILE], nz[ITILE], acc[ITILE];
        #pragma unroll
        for (int t = 0; t < ITILE; t++) {
            const int i = ti * TILE + t * TPB + tid;
            const float ax = xa[i * 3 + 0] * COORD_SCALE;
            const float ay = xa[i * 3 + 1] * COORD_SCALE;
            const float az = xa[i * 3 + 2] * COORD_SCALE;
            const float si = ex2(-0.5f * (ax * ax + ay * ay + az * az));
            const float bx = na[i * 3 + 0] * si;
            const float by = na[i * 3 + 1] * si;
            const float bz = na[i * 3 + 2] * si;
            px[t] = pack2(ax, ax);
            py[t] = pack2(ay, ay);
            pz[t] = pack2(az, az);
            nx[t] = pack2(bx, bx);
            ny[t] = pack2(by, by);
            nz[t] = pack2(bz, bz);
            acc[t] = 0ull;
        }

        // ---- j windows of WIN pairs covering [pj0, pj1) ----
        for (int w0 = pj0 & ~(WIN - 1); w0 < pj1; w0 += WIN) {
            __syncthreads();
            {
                const int j  = tj * TILE + w0 * 2 + tid;
                const float qx = xb[j * 3 + 0] * COORD_SCALE;
                const float qy = xb[j * 3 + 1] * COORD_SCALE;
                const float qz = xb[j * 3 + 2] * COORD_SCALE;
                const float sj = ex2(-0.5f * (qx * qx + qy * qy + qz * qz));
                const float mx = nb[j * 3 + 0] * sj;
                const float my = nb[j * 3 + 1] * sj;
                const float mz = nb[j * 3 + 2] * sj;
                const int jp = tid >> 1;
                const int l  = tid & 1;
                float* base = (float*)&sb[jp * 3];
                base[0 + l]  = qx;  base[2 + l]  = qy;
                base[4 + l]  = qz;  base[6 + l]  = mx;
                base[8 + l]  = my;  base[10 + l] = mz;
            }
            __syncthreads();

            const int lo = (pj0 > w0 ? pj0 : w0) - w0;
            const int hi = (pj1 < w0 + WIN ? pj1 : w0 + WIN) - w0;
            const int n  = hi - lo;

            const ulonglong2* jptr = ((const ulonglong2*)sb) + 3 * lo;
            ulonglong2 c0 = jptr[0], c1 = jptr[1], c2 = jptr[2];
            #pragma unroll 4
            for (int it = 0; it < n; it++) {
                jptr += 3;
                const ulonglong2 n0 = jptr[0];   // pad makes last prefetch safe
                const ulonglong2 n1 = jptr[1];
                const ulonglong2 n2 = jptr[2];

                // a-dots (both i chains)
                ull a0 = mul2(px[0], c0.x);
                ull a1 = mul2(px[1], c0.x);
                a0 = fma2(py[0], c0.y, a0);
                a1 = fma2(py[1], c0.y, a1);
                a0 = fma2(pz[0], c1.x, a0);
                a1 = fma2(pz[1], c1.x, a1);

                // 4 EX2 back-to-back
                float a00, a01, a10, a11;
                unpack2(a0, a00, a01);
                unpack2(a1, a10, a11);
                const float e00 = ex2(a00);
                const float e01 = ex2(a01);
                const float e10 = ex2(a10);
                const float e11 = ex2(a11);

                // d-dots — cover MUFU latency
                ull d0 = mul2(nx[0], c1.y);
                ull d1 = mul2(nx[1], c1.y);
                d0 = fma2(ny[0], c2.x, d0);
                d1 = fma2(ny[1], c2.x, d1);
                d0 = fma2(nz[0], c2.y, d0);
                d1 = fma2(nz[1], c2.y, d1);

                // acc += (2^a * D')^2
                const ull e0 = pack2(e00, e01);
                const ull e1 = pack2(e10, e11);
                const ull t0 = mul2(e0, d0);
                const ull t1 = mul2(e1, d1);
                acc[0] = fma2(t0, t0, acc[0]);
                acc[1] = fma2(t1, t1, acc[1]);

                c0 = n0; c1 = n1; c2 = n2;
            }
        }

        #pragma unroll
        for (int t = 0; t < ITILE; t++) {
            float a0, a1;
            unpack2(acc[t], a0, a1);
            vsum += w * (a0 + a1);
        }

        p += (ull)(pj1 - pj0);
    }

    // ---- block reduction (deterministic) ----
    float v = vsum;
    #pragma unroll
    for (int o = 16; o > 0; o >>= 1)
        v += __shfl_xor_sync(0xffffffffu, v, o);
    if ((tid & 31) == 0) warpsum[tid >> 5] = v;
    __syncthreads();

    __shared__ bool is_last;
    if (tid == 0) {
        float s = 0.0f;
        #pragma unroll
        for (int k = 0; k < TPB / 32; k++) s += warpsum[k];
        g_partials[bid] = s;
        __threadfence();
        const unsigned int done = atomicAdd(&g_count, 1u);
        is_last = (done == (unsigned int)(NBLK - 1));
    }
    __syncthreads();

    // ---- last block finalizes with a single warp (fixed order => deterministic) ----
    if (is_last && tid < 32) {
        float r = 0.0f;
        for (int i = tid; i < NBLK; i += 32)
            r += __ldcg(&g_partials[i]);
        #pragma unroll
        for (int o = 16; o > 0; o >>= 1)
            r += __shfl_xor_sync(0xffffffffu, r, o);
        if (tid == 0) {
            out[0] = r;
            g_count = 0;   // reset for next graph replay
        }
    }
}

extern "C" void kernel_launch(void* const* d_in, const int* in_sizes, int n_in,
                              void* d_out, int out_size)
{
    const float* xyz1 = (const float*)d_in[0];
    const float* xyz2 = (const float*)d_in[1];
    const float* nor1 = (const float*)d_in[2];
    const float* nor2 = (const float*)d_in[3];

    varifold_fused<<<NBLK, TPB>>>(xyz1, xyz2, nor1, nor2, (float*)d_out);
}

// round 13
// speedup vs baseline: 1.0899x; 1.0899x over previous
#include <cuda_runtime.h>

#define NPTS    4096
#define BATCH   4
#define TPB     256
#define TILE    256                    // square tile side
#define T       (NPTS / TILE)          // 16
#define NSYM    (T * (T + 1) / 2)      // 136
#define NCROSS  (T * T)                // 256
#define PAIRS   (2 * NSYM + NCROSS)    // 528 blocks per batch
#define NBLOCKS (PAIRS * BATCH)        // 2112
#define ISUB    2                      // i sub-tiles per warp (block i = 2*8*16 = 256)
#define JSTEPS  (TILE / 8)             // 32

// sqrt(log2(e)): p = x*SCALE  =>  p_i.p_j = log2(e) * x_i.x_j
#define COORD_SCALE 1.2011224087864498f

__device__ float g_partials[NBLOCKS];
__device__ unsigned int g_count = 0;

__device__ __forceinline__ float ex2(float x) {
    float r;
    asm("ex2.approx.ftz.f32 %0, %1;" : "=f"(r) : "f"(x));
    return r;
}
__device__ __forceinline__ unsigned bfb(float x) {     // bf16 bits (round-nearest)
    unsigned short h;
    asm("cvt.rn.bf16.f32 %0, %1;" : "=h"(h) : "f"(x));
    return (unsigned)h;
}
__device__ __forceinline__ float bf2f(unsigned h) {    // exact bf16 -> f32
    return __uint_as_float(h << 16);
}
#define PK(lo, hi) ((lo) | ((hi) << 16))

// D = A(16x16 bf16, row-major) x B(16x8 bf16, col-major) + 0, fp32 accum
__device__ __forceinline__ void mma16816(
    float& d0, float& d1, float& d2, float& d3,
    unsigned a0, unsigned a1, unsigned a2, unsigned a3,
    unsigned b0, unsigned b1)
{
    asm("mma.sync.aligned.m16n8k16.row.col.f32.bf16.bf16.f32 "
        "{%0,%1,%2,%3}, {%4,%5,%6,%7}, {%8,%9}, {%10,%11,%12,%13};"
        : "=f"(d0), "=f"(d1), "=f"(d2), "=f"(d3)
        : "r"(a0), "r"(a1), "r"(a2), "r"(a3), "r"(b0), "r"(b1),
          "f"(0.0f), "f"(0.0f), "f"(0.0f), "f"(0.0f));
}

// K-vector layouts (16 bf16 = 8 u32 words per point):
// A-side (i): k = [H0,H1,H2, L0,L1,L2, H0,H1,H2, L0,L1,L2, 0,0,0,0]
// B-side (j): k = [H0,H1,H2, H0,H1,H2, L0,L1,L2, L0,L1,L2, 0,0,0,0]
// dot = Hi.Hj + Li.Hj + Hi.Lj + Li.Lj = exact (hi+lo) product

__device__ __forceinline__ void write_A(unsigned* u, float v0, float v1, float v2) {
    const unsigned h0 = bfb(v0), h1 = bfb(v1), h2 = bfb(v2);
    const unsigned l0 = bfb(v0 - bf2f(h0));
    const unsigned l1 = bfb(v1 - bf2f(h1));
    const unsigned l2 = bfb(v2 - bf2f(h2));
    const unsigned w0 = PK(h0, h1), w1 = PK(h2, l0), w2 = PK(l1, l2);
    u[0] = w0; u[1] = w1; u[2] = w2;
    u[3] = w0; u[4] = w1; u[5] = w2;
    u[6] = 0u; u[7] = 0u;
}
__device__ __forceinline__ void write_B(unsigned* u, float v0, float v1, float v2) {
    const unsigned h0 = bfb(v0), h1 = bfb(v1), h2 = bfb(v2);
    const unsigned l0 = bfb(v0 - bf2f(h0));
    const unsigned l1 = bfb(v1 - bf2f(h1));
    const unsigned l2 = bfb(v2 - bf2f(h2));
    u[0] = PK(h0, h1); u[1] = PK(h2, h0); u[2] = PK(h1, h2);
    u[3] = PK(l0, l1); u[4] = PK(l2, l0); u[5] = PK(l1, l2);
    u[6] = 0u; u[7] = 0u;
}

__global__ void __launch_bounds__(TPB, 4)
varifold_mma(const float* __restrict__ xyz1,
             const float* __restrict__ xyz2,
             const float* __restrict__ nor1,
             const float* __restrict__ nor2,
             float* __restrict__ out)
{
    __shared__ unsigned sIP[TILE * 8];   // i position K-vecs (A layout)
    __shared__ unsigned sID[TILE * 8];   // i scaled-normal K-vecs (A layout)
    __shared__ unsigned sJP[TILE * 8];   // j position K-vecs (B layout)
    __shared__ unsigned sJD[TILE * 8];   // j scaled-normal K-vecs (B layout)
    __shared__ float warpsum[TPB / 32];

    const int tid  = threadIdx.x;
    const int wid  = tid >> 5;
    const int lane = tid & 31;
    const int g    = lane >> 2;          // groupID
    const int tig  = lane & 3;           // thread-in-group

    // ---- decode block -> (term, ti, tj, weight) ----
    int idx = blockIdx.x;                // 0..PAIRS-1
    const int b = blockIdx.y;
    int term, ti, tj;
    float w;
    if (idx < 2 * NSYM) {
        term = (idx < NSYM) ? 0 : 1;
        int k = (idx < NSYM) ? idx : idx - NSYM;
        ti = 0;
        while (k >= T - ti) { k -= T - ti; ti++; }
        tj = ti + k;
        w = (ti == tj) ? 1.0f : 2.0f;    // symmetric: off-diag counted twice
    } else {
        term = 2;
        const int q = idx - 2 * NSYM;
        ti = q >> 4;                     // T == 16
        tj = q & (T - 1);
        w = -2.0f;
    }

    const float* xa; const float* xb; const float* na; const float* nb;
    if (term == 0)      { xa = xyz1; xb = xyz1; na = nor1; nb = nor1; }
    else if (term == 1) { xa = xyz2; xb = xyz2; na = nor2; nb = nor2; }
    else                { xa = xyz1; xb = xyz2; na = nor1; nb = nor2; }
    const long boff = (long)b * NPTS * 3;
    xa += boff; xb += boff; na += boff; nb += boff;

    // ---- fill smem K-vectors: thread handles i-point tid and j-point tid ----
    {
        const int ip = ti * TILE + tid;
        const float px = xa[ip * 3 + 0] * COORD_SCALE;
        const float py = xa[ip * 3 + 1] * COORD_SCALE;
        const float pz = xa[ip * 3 + 2] * COORD_SCALE;
        const float si = ex2(-0.5f * (px * px + py * py + pz * pz));
        write_A(&sIP[tid * 8], px, py, pz);
        write_A(&sID[tid * 8], na[ip * 3 + 0] * si, na[ip * 3 + 1] * si, na[ip * 3 + 2] * si);

        const int jp = tj * TILE + tid;
        const float qx = xb[jp * 3 + 0] * COORD_SCALE;
        const float qy = xb[jp * 3 + 1] * COORD_SCALE;
        const float qz = xb[jp * 3 + 2] * COORD_SCALE;
        const float sj = ex2(-0.5f * (qx * qx + qy * qy + qz * qz));
        write_B(&sJP[tid * 8], qx, qy, qz);
        write_B(&sJD[tid * 8], nb[jp * 3 + 0] * sj, nb[jp * 3 + 1] * sj, nb[jp * 3 + 2] * sj);
    }
    __syncthreads();

    // ---- main: per warp, ISUB i-subtiles x 32 j-steps of m16n8k16 ----
    float v0 = 0.0f, v1 = 0.0f, v2 = 0.0f, v3 = 0.0f;

    #pragma unroll
    for (int s = 0; s < ISUB; s++) {
        const int row = s * 128 + wid * 16 + g;
        // A fragments (constant over j): regs {rows g / g+8} x {k 0-7 / 8-15}
        const unsigned aP0 = sIP[row * 8 + tig];
        const unsigned aP1 = sIP[(row + 8) * 8 + tig];
        const unsigned aP2 = sIP[row * 8 + 4 + tig];
        const unsigned aP3 = sIP[(row + 8) * 8 + 4 + tig];
        const unsigned aD0 = sID[row * 8 + tig];
        const unsigned aD1 = sID[(row + 8) * 8 + tig];
        const unsigned aD2 = sID[row * 8 + 4 + tig];
        const unsigned aD3 = sID[(row + 8) * 8 + 4 + tig];

        int jb = g * 8 + tig;            // word index of this lane's B slice
        #pragma unroll 4
        for (int js = 0; js < JSTEPS; js++) {
            const unsigned bp0 = sJP[jb];
            const unsigned bp1 = sJP[jb + 4];
            const unsigned bd0 = sJD[jb];
            const unsigned bd1 = sJD[jb + 4];

            float p0, p1, p2, p3, d0, d1, d2, d3;
            mma16816(p0, p1, p2, p3, aP0, aP1, aP2, aP3, bp0, bp1);
            mma16816(d0, d1, d2, d3, aD0, aD1, aD2, aD3, bd0, bd1);

            // per pair: acc += (2^{p.p} * D')^2 = exp(-S) * D^2
            const float e0 = ex2(p0);
            const float e1 = ex2(p1);
            const float e2 = ex2(p2);
            const float e3 = ex2(p3);
            const float t0 = e0 * d0;
            const float t1 = e1 * d1;
            const float t2 = e2 * d2;
            const float t3 = e3 * d3;
            v0 = fmaf(t0, t0, v0);
            v1 = fmaf(t1, t1, v1);
            v2 = fmaf(t2, t2, v2);
            v3 = fmaf(t3, t3, v3);

            jb += 64;                    // next 8 j-vectors
        }
    }

    // ---- block reduction (deterministic) ----
    float v = w * ((v0 + v1) + (v2 + v3));
    #pragma unroll
    for (int o = 16; o > 0; o >>= 1)
        v += __shfl_xor_sync(0xffffffffu, v, o);
    if ((tid & 31) == 0) warpsum[tid >> 5] = v;
    __syncthreads();

    __shared__ bool is_last;
    if (tid == 0) {
        float s = 0.0f;
        #pragma unroll
        for (int k = 0; k < TPB / 32; k++) s += warpsum[k];
        const int blin = blockIdx.y * gridDim.x + blockIdx.x;
        g_partials[blin] = s;
        __threadfence();
        const unsigned int done = atomicAdd(&g_count, 1u);
        is_last = (done == (unsigned int)(NBLOCKS - 1));
    }
    __syncthreads();

    // ---- last block finalizes (256 threads, fixed order => deterministic) ----
    if (is_last) {
        float r = 0.0f;
        for (int i = tid; i < NBLOCKS; i += TPB)
            r += __ldcg(&g_partials[i]);
        #pragma unroll
        for (int o = 16; o > 0; o >>= 1)
            r += __shfl_xor_sync(0xffffffffu, r, o);
        if ((tid & 31) == 0) warpsum[tid >> 5] = r;
        __syncthreads();
        if (tid == 0) {
            float s = 0.0f;
            #pragma unroll
            for (int k = 0; k < TPB / 32; k++) s += warpsum[k];
            out[0] = s;
            g_count = 0;   // reset for next graph replay
        }
    }
}

extern "C" void kernel_launch(void* const* d_in, const int* in_sizes, int n_in,
                              void* d_out, int out_size)
{
    const float* xyz1 = (const float*)d_in[0];
    const float* xyz2 = (const float*)d_in[1];
    const float* nor1 = (const float*)d_in[2];
    const float* nor2 = (const float*)d_in[3];

    dim3 grid(PAIRS, BATCH);
    varifold_mma<<<grid, TPB>>>(xyz1, xyz2, nor1, nor2, (float*)d_out);
}

// round 14
// speedup vs baseline: 1.4058x; 1.2899x over previous
#include <cuda_runtime.h>

#define NPTS    4096
#define BATCH   4
#define TPB     256
#define TILE    256                    // square tile side
#define T       (NPTS / TILE)          // 16
#define NSYM    (T * (T + 1) / 2)      // 136
#define NCROSS  (T * T)                // 256
#define PAIRS   (2 * NSYM + NCROSS)    // 528 blocks per batch
#define NBLOCKS (PAIRS * BATCH)        // 2112
#define ISUB    2                      // i sub-tiles per warp
#define JSTEPS  (TILE / 8)             // 32

// sqrt(log2(e)): p = x*SCALE  =>  p_i.p_j = log2(e) * x_i.x_j
#define COORD_SCALE 1.2011224087864498f

__device__ float g_partials[NBLOCKS];
__device__ unsigned int g_count = 0;

__device__ __forceinline__ float ex2(float x) {
    float r;
    asm("ex2.approx.ftz.f32 %0, %1;" : "=f"(r) : "f"(x));
    return r;
}
__device__ __forceinline__ unsigned bfb(float x) {     // bf16 bits (round-nearest)
    unsigned short h;
    asm("cvt.rn.bf16.f32 %0, %1;" : "=h"(h) : "f"(x));
    return (unsigned)h;
}
__device__ __forceinline__ float bf2f(unsigned h) {    // exact bf16 -> f32
    return __uint_as_float(h << 16);
}
#define PK(lo, hi) ((lo) | ((hi) << 16))

// D = A(16x16 bf16, row-major) x B(16x8 bf16, col-major) + 0, fp32 accum
__device__ __forceinline__ void mma16816(
    float& d0, float& d1, float& d2, float& d3,
    unsigned a0, unsigned a1, unsigned a2, unsigned a3,
    unsigned b0, unsigned b1)
{
    asm("mma.sync.aligned.m16n8k16.row.col.f32.bf16.bf16.f32 "
        "{%0,%1,%2,%3}, {%4,%5,%6,%7}, {%8,%9}, {%10,%11,%12,%13};"
        : "=f"(d0), "=f"(d1), "=f"(d2), "=f"(d3)
        : "r"(a0), "r"(a1), "r"(a2), "r"(a3), "r"(b0), "r"(b1),
          "f"(0.0f), "f"(0.0f), "f"(0.0f), "f"(0.0f));
}

// K-vector layouts (16 bf16 = 8 u32 words per point):
// A-side (i): k = [H0,H1,H2, L0,L1,L2, H0,H1,H2, L0,L1,L2, 0,0,0,0]
// B-side (j): k = [H0,H1,H2, H0,H1,H2, L0,L1,L2, L0,L1,L2, 0,0,0,0]
//   stored PAIRED: [w0,w4, w1,w5, w2,w6, w3,w7] so lane tig reads its two
//   fragment words (tig, tig+4) with one LDS.64 at word offset tig*2.
// dot = Hi.Hj + Li.Hj + Hi.Lj + Li.Lj = exact (hi+lo)x(hi+lo) product

__device__ __forceinline__ void write_A(unsigned* u, float v0, float v1, float v2) {
    const unsigned h0 = bfb(v0), h1 = bfb(v1), h2 = bfb(v2);
    const unsigned l0 = bfb(v0 - bf2f(h0));
    const unsigned l1 = bfb(v1 - bf2f(h1));
    const unsigned l2 = bfb(v2 - bf2f(h2));
    const unsigned w0 = PK(h0, h1), w1 = PK(h2, l0), w2 = PK(l1, l2);
    u[0] = w0; u[1] = w1; u[2] = w2;
    u[3] = w0; u[4] = w1; u[5] = w2;
    u[6] = 0u; u[7] = 0u;
}
__device__ __forceinline__ void write_B_paired(unsigned* u, float v0, float v1, float v2) {
    const unsigned h0 = bfb(v0), h1 = bfb(v1), h2 = bfb(v2);
    const unsigned l0 = bfb(v0 - bf2f(h0));
    const unsigned l1 = bfb(v1 - bf2f(h1));
    const unsigned l2 = bfb(v2 - bf2f(h2));
    // original words: w0=PK(h0,h1) w1=PK(h2,h0) w2=PK(h1,h2)
    //                 w3=PK(l0,l1) w4=PK(l2,l0) w5=PK(l1,l2) w6=w7=0
    u[0] = PK(h0, h1);  u[1] = PK(l2, l0);   // (w0, w4)
    u[2] = PK(h2, h0);  u[3] = PK(l1, l2);   // (w1, w5)
    u[4] = PK(h1, h2);  u[5] = 0u;           // (w2, w6)
    u[6] = PK(l0, l1);  u[7] = 0u;           // (w3, w7)
}

__global__ void __launch_bounds__(TPB, 4)
varifold_mma(const float* __restrict__ xyz1,
             const float* __restrict__ xyz2,
             const float* __restrict__ nor1,
             const float* __restrict__ nor2,
             float* __restrict__ out)
{
    __shared__ unsigned sIP[TILE * 8];   // i position K-vecs (A layout)
    __shared__ unsigned sID[TILE * 8];   // i scaled-normal K-vecs (A layout)
    __shared__ __align__(8) unsigned sJP[TILE * 8];   // j position K-vecs (B paired)
    __shared__ __align__(8) unsigned sJD[TILE * 8];   // j scaled-normal K-vecs (B paired)
    __shared__ float warpsum[TPB / 32];

    const int tid  = threadIdx.x;
    const int wid  = tid >> 5;
    const int lane = tid & 31;
    const int g    = lane >> 2;          // groupID
    const int tig  = lane & 3;           // thread-in-group

    // ---- decode block -> (term, ti, tj, weight) ----
    int idx = blockIdx.x;                // 0..PAIRS-1
    const int b = blockIdx.y;
    int term, ti, tj;
    float w;
    if (idx < 2 * NSYM) {
        term = (idx < NSYM) ? 0 : 1;
        int k = (idx < NSYM) ? idx : idx - NSYM;
        ti = 0;
        while (k >= T - ti) { k -= T - ti; ti++; }
        tj = ti + k;
        w = (ti == tj) ? 1.0f : 2.0f;    // symmetric: off-diag counted twice
    } else {
        term = 2;
        const int q = idx - 2 * NSYM;
        ti = q >> 4;                     // T == 16
        tj = q & (T - 1);
        w = -2.0f;
    }

    const float* xa; const float* xb; const float* na; const float* nb;
    if (term == 0)      { xa = xyz1; xb = xyz1; na = nor1; nb = nor1; }
    else if (term == 1) { xa = xyz2; xb = xyz2; na = nor2; nb = nor2; }
    else                { xa = xyz1; xb = xyz2; na = nor1; nb = nor2; }
    const long boff = (long)b * NPTS * 3;
    xa += boff; xb += boff; na += boff; nb += boff;

    // ---- fill smem K-vectors: thread handles i-point tid and j-point tid ----
    {
        const int ip = ti * TILE + tid;
        const float px = xa[ip * 3 + 0] * COORD_SCALE;
        const float py = xa[ip * 3 + 1] * COORD_SCALE;
        const float pz = xa[ip * 3 + 2] * COORD_SCALE;
        const float si = ex2(-0.5f * (px * px + py * py + pz * pz));
        write_A(&sIP[tid * 8], px, py, pz);
        write_A(&sID[tid * 8], na[ip * 3 + 0] * si, na[ip * 3 + 1] * si, na[ip * 3 + 2] * si);

        const int jp = tj * TILE + tid;
        const float qx = xb[jp * 3 + 0] * COORD_SCALE;
        const float qy = xb[jp * 3 + 1] * COORD_SCALE;
        const float qz = xb[jp * 3 + 2] * COORD_SCALE;
        const float sj = ex2(-0.5f * (qx * qx + qy * qy + qz * qz));
        write_B_paired(&sJP[tid * 8], qx, qy, qz);
        write_B_paired(&sJD[tid * 8], nb[jp * 3 + 0] * sj, nb[jp * 3 + 1] * sj, nb[jp * 3 + 2] * sj);
    }
    __syncthreads();

    // ---- hoist A fragments for BOTH i-subtiles (held across the j loop) ----
    unsigned aP[ISUB][4], aD[ISUB][4];
    #pragma unroll
    for (int s = 0; s < ISUB; s++) {
        const int row = s * 128 + wid * 16 + g;
        aP[s][0] = sIP[row * 8 + tig];
        aP[s][1] = sIP[(row + 8) * 8 + tig];
        aP[s][2] = sIP[row * 8 + 4 + tig];
        aP[s][3] = sIP[(row + 8) * 8 + 4 + tig];
        aD[s][0] = sID[row * 8 + tig];
        aD[s][1] = sID[(row + 8) * 8 + tig];
        aD[s][2] = sID[row * 8 + 4 + tig];
        aD[s][3] = sID[(row + 8) * 8 + 4 + tig];
    }

    // ---- main loop: js outer, B loaded ONCE per step (2x LDS.64) ----
    float v0 = 0.0f, v1 = 0.0f, v2 = 0.0f, v3 = 0.0f;

    int jb = g * 8 + tig * 2;            // paired layout: lane's LDS.64 word offset
    #pragma unroll 4
    for (int js = 0; js < JSTEPS; js++) {
        const uint2 bp = *(const uint2*)&sJP[jb];   // (b0, b1) position
        const uint2 bd = *(const uint2*)&sJD[jb];   // (b0, b1) normal

        #pragma unroll
        for (int s = 0; s < ISUB; s++) {
            float p0, p1, p2, p3, d0, d1, d2, d3;
            mma16816(p0, p1, p2, p3, aP[s][0], aP[s][1], aP[s][2], aP[s][3], bp.x, bp.y);
            mma16816(d0, d1, d2, d3, aD[s][0], aD[s][1], aD[s][2], aD[s][3], bd.x, bd.y);

            const float e0 = ex2(p0);
            const float e1 = ex2(p1);
            const float e2 = ex2(p2);
            const float e3 = ex2(p3);
            const float t0 = e0 * d0;
            const float t1 = e1 * d1;
            const float t2 = e2 * d2;
            const float t3 = e3 * d3;
            v0 = fmaf(t0, t0, v0);
            v1 = fmaf(t1, t1, v1);
            v2 = fmaf(t2, t2, v2);
            v3 = fmaf(t3, t3, v3);
        }
        jb += 64;                        // next 8 j-vectors
    }

    // ---- block reduction (deterministic) ----
    float v = w * ((v0 + v1) + (v2 + v3));
    #pragma unroll
    for (int o = 16; o > 0; o >>= 1)
        v += __shfl_xor_sync(0xffffffffu, v, o);
    if ((tid & 31) == 0) warpsum[tid >> 5] = v;
    __syncthreads();

    __shared__ bool is_last;
    if (tid == 0) {
        float s = 0.0f;
        #pragma unroll
        for (int k = 0; k < TPB / 32; k++) s += warpsum[k];
        const int blin = blockIdx.y * gridDim.x + blockIdx.x;
        g_partials[blin] = s;
        __threadfence();
        const unsigned int done = atomicAdd(&g_count, 1u);
        is_last = (done == (unsigned int)(NBLOCKS - 1));
    }
    __syncthreads();

    // ---- last block finalizes (fixed order => deterministic) ----
    if (is_last) {
        float r = 0.0f;
        for (int i = tid; i < NBLOCKS; i += TPB)
            r += __ldcg(&g_partials[i]);
        #pragma unroll
        for (int o = 16; o > 0; o >>= 1)
            r += __shfl_xor_sync(0xffffffffu, r, o);
        if ((tid & 31) == 0) warpsum[tid >> 5] = r;
        __syncthreads();
        if (tid == 0) {
            float s = 0.0f;
            #pragma unroll
            for (int k = 0; k < TPB / 32; k++) s += warpsum[k];
            out[0] = s;
            g_count = 0;   // reset for next graph replay
        }
    }
}

extern "C" void kernel_launch(void* const* d_in, const int* in_sizes, int n_in,
                              void* d_out, int out_size)
{
    const float* xyz1 = (const float*)d_in[0];
    const float* xyz2 = (const float*)d_in[1];
    const float* nor1 = (const float*)d_in[2];
    const float* nor2 = (const float*)d_in[3];

    dim3 grid(PAIRS, BATCH);
    varifold_mma<<<grid, TPB>>>(xyz1, xyz2, nor1, nor2, (float*)d_out);
}